// round 7
// baseline (speedup 1.0000x reference)
#include <cuda_runtime.h>
#include <math.h>
#include <stdint.h>

#define BB 4
#define CC 256
#define HH 128
#define WW 128
#define AA 9
#define NPOS (HH*WW)          // 16384
#define NANCH (NPOS*AA)       // 147456
#define PRE_K 600
#define POST_K 100
#define NMS_WORDS 19          // ceil(600/32)
#define BINS 4096
#define BIN_SHIFT 20
#define CAP 2048

typedef unsigned long long u64;

// ---------------- scratch (device globals; no allocation allowed) ----------
__device__ __align__(16) float d_t[BB*CC*NPOS];          // conv+relu output, 64 MB
__device__ __align__(16) float d_scores[BB*NANCH];       // 2.25 MB
__device__ __align__(16) float d_deltas[BB*NANCH*4];     // 9 MB
__device__ __align__(16) float d_wt[4*32*72*64];         // transposed conv weights
__device__ unsigned int d_hist[BB][BINS];
__device__ int d_thrbin[BB];
__device__ int d_candcnt[BB];
__device__ unsigned long long d_cand[BB][CAP];
__device__ __align__(16) float d_boxes[BB][PRE_K*4];
__device__ unsigned int d_mask[BB][PRE_K*NMS_WORDS];

// anchor half-sizes, a = scale_idx*3 + ratio_idx, computed in double then fp32
__constant__ float c_hw[9] = {
    45.25483399593904f,  64.0f, 90.50966799187808f,
    90.50966799187808f, 128.0f, 181.01933598375617f,
    181.01933598375617f,256.0f, 362.03867196751233f};
__constant__ float c_hh[9] = {
    90.50966799187808f,  64.0f, 45.25483399593904f,
    181.01933598375617f,128.0f, 90.50966799187808f,
    362.03867196751233f,256.0f, 181.01933598375617f};

// conv smem (floats): tile 8 rows x 16 cols, halo 10x18, 8 ci per chunk
#define CONV_SA_STAGE (8*10*18)            // 1440 floats per stage
#define CONV_SB_STAGE (72*64)              // 4608 floats per stage
#define CONV_SMEM_BYTES ((2*CONV_SA_STAGE + 2*CONV_SB_STAGE)*4)   // 48384

// heads: 15 outs/group (padded to 16 in smem), 3 groups
#define HOG 15
#define HOGP 16
#define HEADS_SMEM_BYTES (256*HOGP*8 + 64 + BINS*4)               // 49216

// ---------------- packed f32x2 helpers (Blackwell) --------------------------
__device__ __forceinline__ u64 pack2(float x) {
    u64 r;
    asm("mov.b64 %0, {%1, %1};" : "=l"(r) : "f"(x));
    return r;
}
__device__ __forceinline__ void fma2(u64& d, u64 a, u64 b) {
    asm("fma.rn.f32x2 %0, %1, %2, %0;" : "+l"(d) : "l"(a), "l"(b));
}
__device__ __forceinline__ void unpack2(u64 a, float& lo, float& hi) {
    asm("mov.b64 {%0, %1}, %2;" : "=f"(lo), "=f"(hi) : "l"(a));
}

// ---------------- cp.async helpers ------------------------------------------
__device__ __forceinline__ void cp_async16(uint32_t s, const void* g) {
    asm volatile("cp.async.cg.shared.global [%0], [%1], 16;" :: "r"(s), "l"(g));
}
__device__ __forceinline__ void cp_async4z(uint32_t s, const void* g, bool ok) {
    int sz = ok ? 4 : 0;
    asm volatile("cp.async.ca.shared.global [%0], [%1], 4, %2;" :: "r"(s), "l"(g), "r"(sz));
}
#define CP_COMMIT()  asm volatile("cp.async.commit_group;" ::: "memory")
#define CP_WAIT1()   asm volatile("cp.async.wait_group 1;" ::: "memory")
#define CP_WAIT0()   asm volatile("cp.async.wait_group 0;" ::: "memory")

// ---------------- K0: weight transpose --------------------------------------
__global__ void k_wt(const float* __restrict__ w) {
    int idx = blockIdx.x*1024 + threadIdx.x;
    if (idx >= 4*32*72*64) return;
    int co = idx & 63; int t = idx >> 6;
    int r = t % 72; t /= 72;
    int cb8 = t & 31; int g = t >> 5;
    d_wt[idx] = w[(g*64 + co)*2304 + cb8*72 + r];
}

// ---------------- K1: 3x3 conv (256->256) + ReLU -----------------------------
// tile 8x16 px, 64 co. grid (8,16,16): x=tile-x, y=tile-y, z=b*4+g. occ 3.
// thread = pg(0..31)*8 + cg(0..7); pr=pg>>2 (0..7), pc=(pg&3)*4; 4 px, 8 co.
__global__ __launch_bounds__(256, 3)
void k_conv3(const float* __restrict__ f, const float* __restrict__ bias)
{
    extern __shared__ __align__(16) float smem[];
    float* sA = smem;                                   // 2 stages x 1440 floats
    float* sB = smem + 2*CONV_SA_STAGE;                 // 2 stages x 4608 floats

    const int tid = threadIdx.x;
    const int pg = tid >> 3, cg = tid & 7;
    const int pr = pg >> 2, pc = (pg & 3) * 4;
    const int b = blockIdx.z >> 2;
    const int g = blockIdx.z & 3;
    const int co_base = g * 64;
    const int x0 = blockIdx.x * 16, y0 = blockIdx.y * 8;

    const uint32_t sA0 = (uint32_t)__cvta_generic_to_shared(sA);
    const uint32_t sB0 = (uint32_t)__cvta_generic_to_shared(sB);

    u64 acc2[4][4];   // [px m][co pair jp]
    #pragma unroll
    for (int m = 0; m < 4; m++)
        #pragma unroll
        for (int jp = 0; jp < 4; jp++) acc2[m][jp] = 0ULL;

    auto load_stage = [&](int st, int cb8) {
        const uint32_t sa = sA0 + st * (CONV_SA_STAGE*4);
        // halo: 8ci x 10 x 18 floats
        for (int e = tid; e < 8*10*18; e += 256) {
            int ci = e / 180; int rem = e - ci*180;
            int yy = rem / 18; int xx = rem - yy*18;
            int gy = y0 + yy - 1, gx = x0 + xx - 1;
            bool ok = (gy >= 0 && gy < 128 && gx >= 0 && gx < 128);
            int cy = gy < 0 ? 0 : (gy > 127 ? 127 : gy);
            int cx = gx < 0 ? 0 : (gx > 127 ? 127 : gx);
            cp_async4z(sa + e*4, &f[((b*256 + cb8*8 + ci)*128 + cy)*128 + cx], ok);
        }
        const float* ws = &d_wt[((g*32 + cb8)*72)*64];
        const uint32_t sb = sB0 + st * (CONV_SB_STAGE*4);
        for (int e = tid*4; e < 72*64; e += 1024)
            cp_async16(sb + e*4, ws + e);
    };

    load_stage(0, 0);
    CP_COMMIT();

    for (int cb8 = 0; cb8 < 32; cb8++) {
        const int cur = cb8 & 1;
        if (cb8 + 1 < 32) {
            load_stage(cur ^ 1, cb8 + 1);
            CP_COMMIT();
            CP_WAIT1();
        } else {
            CP_WAIT0();
        }
        __syncthreads();

        const float* sAc = sA + cur*CONV_SA_STAGE;
        const float* sBc = sB + cur*CONV_SB_STAGE;

        #pragma unroll
        for (int ci = 0; ci < 8; ci++) {
            #pragma unroll
            for (int ky = 0; ky < 3; ky++) {
                u64 aw[6];
                #pragma unroll
                for (int m = 0; m < 6; m++)
                    aw[m] = pack2(sAc[ci*180 + (pr + ky)*18 + pc + m]);
                #pragma unroll
                for (int kx = 0; kx < 3; kx++) {
                    const int kk = ci*9 + ky*3 + kx;
                    const ulonglong2 b01 = *(const ulonglong2*)&sBc[kk*64 + cg*8];
                    const ulonglong2 b23 = *(const ulonglong2*)&sBc[kk*64 + cg*8 + 4];
                    #pragma unroll
                    for (int m = 0; m < 4; m++) {
                        fma2(acc2[m][0], aw[kx + m], b01.x);
                        fma2(acc2[m][1], aw[kx + m], b01.y);
                        fma2(acc2[m][2], aw[kx + m], b23.x);
                        fma2(acc2[m][3], aw[kx + m], b23.y);
                    }
                }
            }
        }
        __syncthreads();
    }

    // epilogue: unpack, +bias, relu, float4 stores (pc is 4-aligned)
    #pragma unroll
    for (int jp = 0; jp < 4; jp++) {
        const int co0 = co_base + cg*8 + jp*2;
        const float b0 = bias[co0], b1 = bias[co0 + 1];
        float v0[4], v1[4];
        #pragma unroll
        for (int m = 0; m < 4; m++) {
            float lo, hi;
            unpack2(acc2[m][jp], lo, hi);
            v0[m] = fmaxf(lo + b0, 0.f);
            v1[m] = fmaxf(hi + b1, 0.f);
        }
        float* p0 = &d_t[((b*256 + co0)*128 + (y0 + pr))*128 + (x0 + pc)];
        float* p1 = p0 + NPOS;
        *(float4*)p0 = make_float4(v0[0], v0[1], v0[2], v0[3]);
        *(float4*)p1 = make_float4(v1[0], v1[1], v1[2], v1[3]);
    }
}

// ---------------- selection helpers ----------------------------------------
__device__ __forceinline__ unsigned fkey(float s) {
    unsigned b = __float_as_uint(s);
    return (b & 0x80000000u) ? ~b : (b | 0x80000000u);  // monotone
}

// ---------------- K2: 1x1 heads, 15-out x 2-px, MLP-4 ----------------------
// grid (32, 3, 4): x = px-block (512 px), y = out-group, z = img. 256 thr.
__global__ __launch_bounds__(256)
void k_heads(const float* __restrict__ cls_w, const float* __restrict__ cls_b,
             const float* __restrict__ bbox_w, const float* __restrict__ bbox_b)
{
    extern __shared__ __align__(16) u64 hsm[];
    u64* swd = hsm;                              // [256][16] duplicated weights
    float* sb = (float*)(hsm + 256*HOGP);        // [15] bias (+pad)
    unsigned* shist = (unsigned*)(sb + 16);      // [4096] (group 0 only)

    const int tid = threadIdx.x;
    const int g = blockIdx.y;
    const int b = blockIdx.z;

    for (int e = tid; e < 256*HOGP; e += 256) {
        int o = e & 15, c = e >> 4;
        float w = 0.f;
        if (o < HOG) {
            int ch = g*HOG + o;
            w = (ch < 9) ? cls_w[ch*256 + c] : bbox_w[(ch - 9)*256 + c];
        }
        swd[c*HOGP + o] = pack2(w);
    }
    if (tid < HOG) {
        int ch = g*HOG + tid;
        sb[tid] = (ch < 9) ? cls_b[ch] : bbox_b[ch - 9];
    }
    if (g == 0)
        for (int e = tid; e < BINS; e += 256) shist[e] = 0u;
    __syncthreads();

    const int px0 = blockIdx.x * 512 + tid * 2;

    u64 acc[HOG];
    #pragma unroll
    for (int o = 0; o < HOG; o++) acc[o] = 0ULL;

    const float* tbase = d_t + (size_t)b*CC*NPOS + px0;
    for (int c = 0; c < 256; c += 4) {
        u64 t[4];
        #pragma unroll
        for (int q = 0; q < 4; q++)
            t[q] = *(const u64*)(tbase + (size_t)(c + q)*NPOS);
        #pragma unroll
        for (int q = 0; q < 4; q++) {
            const u64* wr = &swd[(c + q)*HOGP];
            #pragma unroll
            for (int op = 0; op < 8; op++) {
                const ulonglong2 wv = *(const ulonglong2*)&wr[op*2];
                fma2(acc[op*2], t[q], wv.x);
                if (op*2 + 1 < HOG) fma2(acc[op*2 + 1], t[q], wv.y);
            }
        }
    }

    #pragma unroll
    for (int o = 0; o < HOG; o++) {
        const int ch = g*HOG + o;
        const float bv = sb[o];
        float v0, v1;
        unpack2(acc[o], v0, v1);
        if (ch < 9) {
            const float s0 = v0 + bv, s1 = v1 + bv;
            d_scores[(size_t)b*NANCH + (size_t)px0*9 + ch] = s0;
            d_scores[(size_t)b*NANCH + (size_t)(px0 + 1)*9 + ch] = s1;
            atomicAdd(&shist[fkey(s0) >> BIN_SHIFT], 1u);
            atomicAdd(&shist[fkey(s1) >> BIN_SHIFT], 1u);
        } else {
            const int dch = ch - 9;
            d_deltas[(size_t)b*NANCH*4 + (size_t)px0*36 + dch] = v0 + bv;
            d_deltas[(size_t)b*NANCH*4 + (size_t)(px0 + 1)*36 + dch] = v1 + bv;
        }
    }

    if (g == 0) {
        __syncthreads();
        for (int e = tid; e < BINS; e += 256)
            if (shist[e]) atomicAdd(&d_hist[b][e], shist[e]);
    }
}

__global__ void k_init() {
    int id = blockIdx.x * blockDim.x + threadIdx.x;
    if (id < BB*BINS) (&d_hist[0][0])[id] = 0u;
    if (id < BB) d_candcnt[id] = 0;
}

// suffix-sum over 4096 bins, pick highest bin with cum>=600
__global__ __launch_bounds__(1024) void k_thresh() {
    __shared__ unsigned suf[BINS + 1];
    const int tid = threadIdx.x;
    const int b = blockIdx.x;
    for (int e = tid; e < BINS; e += 1024) suf[e] = d_hist[b][e];
    if (tid == 0) suf[BINS] = 0u;
    __syncthreads();
    for (int off = 1; off < BINS; off <<= 1) {
        unsigned add[4];
        #pragma unroll
        for (int q = 0; q < 4; q++) {
            int i = tid + q*1024;
            add[q] = (i + off <= BINS) ? suf[i + off] : 0u;
        }
        __syncthreads();
        #pragma unroll
        for (int q = 0; q < 4; q++) suf[tid + q*1024] += add[q];
        __syncthreads();
    }
    #pragma unroll
    for (int q = 0; q < 4; q++) {
        int i = tid + q*1024;
        if (i < BINS && suf[i] >= PRE_K && suf[i+1] < PRE_K) d_thrbin[b] = i;
    }
}

__global__ void k_compact() {
    const int b = blockIdx.y;
    const int T = d_thrbin[b];
    const float* s = d_scores + (size_t)b*NANCH;
    for (unsigned i = blockIdx.x*blockDim.x + threadIdx.x; i < NANCH; i += gridDim.x*blockDim.x) {
        unsigned u = fkey(s[i]);
        if ((int)(u >> BIN_SHIFT) >= T) {
            int pos = atomicAdd(&d_candcnt[b], 1);
            if (pos < CAP)
                d_cand[b][pos] = ((unsigned long long)u << 32) | (unsigned)(~i);
        }
    }
}

__device__ __forceinline__ float read_dim(const void* p) {
    int i = *(const int*)p;
    float f = __int_as_float(i);
    return (i > 0 && i < (1 << 20)) ? (float)i : f;
}

// per-image: bitonic sort candidates desc by (score, then lower idx), decode top-600
__global__ __launch_bounds__(1024) void k_sortdecode(const void* ph, const void* pw) {
    __shared__ unsigned long long key[CAP];
    const int b = blockIdx.x;
    const int tid = threadIdx.x;
    int n = d_candcnt[b]; if (n > CAP) n = CAP;
    for (int e = tid; e < CAP; e += 1024) key[e] = (e < n) ? d_cand[b][e] : 0ULL;
    __syncthreads();

    for (int k = 2; k <= CAP; k <<= 1) {
        for (int j = k >> 1; j > 0; j >>= 1) {
            const int t = tid;
            const int i = ((t & ~(j - 1)) << 1) | (t & (j - 1));
            const int ixj = i | j;
            unsigned long long a = key[i], c = key[ixj];
            const bool up = ((i & k) == 0);
            if (up ? (a < c) : (a > c)) { key[i] = c; key[ixj] = a; }
            __syncthreads();
        }
    }

    if (tid < PRE_K) {
        const float img_h = read_dim(ph);
        const float img_w = read_dim(pw);
        const unsigned idx = ~(unsigned)(key[tid] & 0xFFFFFFFFULL);
        const int p = idx / 9, a = idx - 9*p;
        const float gx = (float)(p & 127) * 16.0f;
        const float gy = (float)(p >> 7) * 16.0f;
        const float hw = c_hw[a], hh = c_hh[a];
        const float x1 = gx - hw, y1 = gy - hh, x2 = gx + hw, y2 = gy + hh;
        const float w = x2 - x1, h = y2 - y1;
        const float cx = x1 + 0.5f*w, cy = y1 + 0.5f*h;
        const float4 dd = *(const float4*)&d_deltas[((size_t)b*NANCH + idx)*4];
        const float pcx = cx + dd.x * w;
        const float pcy = cy + dd.y * h;
        const float pw2 = w * expf(dd.z);
        const float ph2 = h * expf(dd.w);
        float4 o;
        o.x = fminf(fmaxf(pcx - 0.5f*pw2, 0.f), img_w);
        o.y = fminf(fmaxf(pcy - 0.5f*ph2, 0.f), img_h);
        o.z = fminf(fmaxf(pcx + 0.5f*pw2, 0.f), img_w);
        o.w = fminf(fmaxf(pcy + 0.5f*ph2, 0.f), img_h);
        *(float4*)&d_boxes[b][tid*4] = o;
    }
}

// 600x600 IoU suppression bitmask (j>i direction)
__global__ void k_mask() {
    const int id = blockIdx.x*blockDim.x + threadIdx.x;
    const int b = blockIdx.y;
    if (id >= PRE_K*NMS_WORDS) return;
    const int i = id / NMS_WORDS, wrd = id - i*NMS_WORDS;
    const float4 bi = *(const float4*)&d_boxes[b][i*4];
    const float areai = (bi.z - bi.x) * (bi.w - bi.y);
    unsigned m = 0u;
    const int j0 = wrd * 32;
    #pragma unroll 4
    for (int jj = 0; jj < 32; jj++) {
        const int j = j0 + jj;
        if (j > i && j < PRE_K) {
            const float4 bj = *(const float4*)&d_boxes[b][j*4];
            const float areaj = (bj.z - bj.x) * (bj.w - bj.y);
            const float xx1 = fmaxf(bi.x, bj.x), yy1 = fmaxf(bi.y, bj.y);
            const float xx2 = fminf(bi.z, bj.z), yy2 = fminf(bi.w, bj.w);
            const float inter = fmaxf(xx2 - xx1, 0.f) * fmaxf(yy2 - yy1, 0.f);
            const float iou = inter / (areai + areaj - inter);
            if (iou > 0.7f) m |= (1u << jj);
        }
    }
    d_mask[b][id] = m;
}

// serial suppression pass (single warp) + emit first 100 kept boxes
__global__ __launch_bounds__(128) void k_nms_out(float* __restrict__ out) {
    __shared__ unsigned smask[PRE_K*NMS_WORDS];
    __shared__ unsigned skeep[NMS_WORDS];
    __shared__ int s_sel[POST_K];
    __shared__ int s_cnt;
    const int b = blockIdx.x;
    const int tid = threadIdx.x;
    for (int e = tid; e < PRE_K*NMS_WORDS; e += 128) smask[e] = d_mask[b][e];
    __syncthreads();

    if (tid < 32) {
        unsigned rm = 0u;
        for (int i = 0; i < PRE_K; i++) {
            const unsigned wb = __shfl_sync(0xFFFFFFFFu, rm, i >> 5);
            if (!((wb >> (i & 31)) & 1u)) {
                if (tid < NMS_WORDS) rm |= smask[i*NMS_WORDS + tid];
            }
        }
        if (tid < NMS_WORDS) skeep[tid] = rm;
    }
    __syncthreads();
    if (tid == 0) {
        int cnt = 0;
        for (int j = 0; j < PRE_K && cnt < POST_K; j++)
            if (!((skeep[j >> 5] >> (j & 31)) & 1u)) s_sel[cnt++] = j;
        s_cnt = cnt;
    }
    __syncthreads();
    const int cnt = s_cnt;
    for (int k = tid; k < POST_K; k += 128) {
        float4 v = make_float4(0.f, 0.f, 0.f, 0.f);
        if (k < cnt) v = *(const float4*)&d_boxes[b][s_sel[k]*4];
        *(float4*)&out[(b*POST_K + k)*4] = v;
    }
}

// ---------------- launch ----------------------------------------------------
extern "C" void kernel_launch(void* const* d_in, const int* in_sizes, int n_in,
                              void* d_out, int out_size)
{
    const float* feats  = (const float*)d_in[0];
    const float* conv_w = (const float*)d_in[1];
    const float* conv_b = (const float*)d_in[2];
    const float* cls_w  = (const float*)d_in[3];
    const float* cls_b  = (const float*)d_in[4];
    const float* bbox_w = (const float*)d_in[5];
    const float* bbox_b = (const float*)d_in[6];
    const void*  ih     = d_in[7];
    const void*  iw     = d_in[8];

    cudaFuncSetAttribute(k_conv3, cudaFuncAttributeMaxDynamicSharedMemorySize,
                         CONV_SMEM_BYTES);
    cudaFuncSetAttribute(k_heads, cudaFuncAttributeMaxDynamicSharedMemorySize,
                         HEADS_SMEM_BYTES);

    k_init<<<64, 256>>>();
    k_wt<<<576, 1024>>>(conv_w);
    k_conv3<<<dim3(8, 16, 16), 256, CONV_SMEM_BYTES>>>(feats, conv_b);
    k_heads<<<dim3(32, 3, 4), 256, HEADS_SMEM_BYTES>>>(cls_w, cls_b, bbox_w, bbox_b);
    k_thresh<<<4, 1024>>>();
    k_compact<<<dim3(64, 4), 256>>>();
    k_sortdecode<<<4, 1024>>>(ih, iw);
    k_mask<<<dim3((PRE_K*NMS_WORDS + 255)/256, 4), 256>>>();
    k_nms_out<<<4, 128>>>((float*)d_out);
}

// round 8
// speedup vs baseline: 1.7151x; 1.7151x over previous
#include <cuda_runtime.h>
#include <math.h>
#include <stdint.h>

#define BB 4
#define CC 256
#define HH 128
#define WW 128
#define AA 9
#define NPOS (HH*WW)          // 16384
#define NANCH (NPOS*AA)       // 147456
#define PRE_K 600
#define POST_K 100
#define NMS_WORDS 19          // ceil(600/32)
#define BINS 4096
#define BIN_SHIFT 20
#define CAP 2048

typedef unsigned long long u64;

// ---------------- scratch (device globals; no allocation allowed) ----------
__device__ __align__(16) float d_t[BB*CC*NPOS];          // conv+relu output, 64 MB
__device__ __align__(16) float d_scores[BB*NANCH];       // 2.25 MB
__device__ __align__(16) float d_deltas[BB*NANCH*4];     // 9 MB
__device__ __align__(16) float d_wt[4*32*72*64];         // transposed conv weights
__device__ unsigned int d_hist[BB][BINS];
__device__ int d_thrbin[BB];
__device__ int d_candcnt[BB];
__device__ unsigned long long d_cand[BB][CAP];
__device__ __align__(16) float d_boxes[BB][PRE_K*4];
__device__ unsigned int d_mask[BB][PRE_K*NMS_WORDS];

// anchor half-sizes, a = scale_idx*3 + ratio_idx, computed in double then fp32
__constant__ float c_hw[9] = {
    45.25483399593904f,  64.0f, 90.50966799187808f,
    90.50966799187808f, 128.0f, 181.01933598375617f,
    181.01933598375617f,256.0f, 362.03867196751233f};
__constant__ float c_hh[9] = {
    90.50966799187808f,  64.0f, 45.25483399593904f,
    181.01933598375617f,128.0f, 90.50966799187808f,
    362.03867196751233f,256.0f, 181.01933598375617f};

// conv smem (floats): R5 config — tile 16x16, halo 18x18, 8 ci per chunk, occ 2
#define CONV_SA_STAGE (8*18*18)            // 2592 floats per stage
#define CONV_SB_STAGE (72*64)              // 4608 floats per stage
#define CONV_SMEM_BYTES ((2*CONV_SA_STAGE + 2*CONV_SB_STAGE)*4)   // 57600

// heads: 15 outs/group (padded to 16 in smem), 3 groups
#define HOG 15
#define HOGP 16
#define HEADS_SMEM_BYTES (256*HOGP*8 + 64 + BINS*4)               // 49216

// ---------------- packed f32x2 helpers (Blackwell) --------------------------
__device__ __forceinline__ u64 pack2(float x) {
    u64 r;
    asm("mov.b64 %0, {%1, %1};" : "=l"(r) : "f"(x));
    return r;
}
__device__ __forceinline__ void fma2(u64& d, u64 a, u64 b) {
    asm("fma.rn.f32x2 %0, %1, %2, %0;" : "+l"(d) : "l"(a), "l"(b));
}
__device__ __forceinline__ void unpack2(u64 a, float& lo, float& hi) {
    asm("mov.b64 {%0, %1}, %2;" : "=f"(lo), "=f"(hi) : "l"(a));
}

// ---------------- cp.async helpers ------------------------------------------
__device__ __forceinline__ void cp_async16(uint32_t s, const void* g) {
    asm volatile("cp.async.cg.shared.global [%0], [%1], 16;" :: "r"(s), "l"(g));
}
__device__ __forceinline__ void cp_async4z(uint32_t s, const void* g, bool ok) {
    int sz = ok ? 4 : 0;
    asm volatile("cp.async.ca.shared.global [%0], [%1], 4, %2;" :: "r"(s), "l"(g), "r"(sz));
}
#define CP_COMMIT()  asm volatile("cp.async.commit_group;" ::: "memory")
#define CP_WAIT1()   asm volatile("cp.async.wait_group 1;" ::: "memory")
#define CP_WAIT0()   asm volatile("cp.async.wait_group 0;" ::: "memory")

// ---------------- K0: weight transpose --------------------------------------
__global__ void k_wt(const float* __restrict__ w) {
    int idx = blockIdx.x*1024 + threadIdx.x;
    if (idx >= 4*32*72*64) return;
    int co = idx & 63; int t = idx >> 6;
    int r = t % 72; t /= 72;
    int cb8 = t & 31; int g = t >> 5;
    d_wt[idx] = w[(g*64 + co)*2304 + cb8*72 + r];
}

// ---------------- K1: 3x3 conv (256->256) + ReLU (R5 config, occ 2) ---------
// grid (8,8,16): x=tile-x(16px), y=tile-y(16px), z = b*4 + co_group(64ch)
__global__ __launch_bounds__(256, 2)
void k_conv3(const float* __restrict__ f, const float* __restrict__ bias)
{
    extern __shared__ __align__(16) float smem[];
    float* sA = smem;                                   // 2 stages x 2592 floats
    float* sB = smem + 2*CONV_SA_STAGE;                 // 2 stages x 4608 floats

    const int tid = threadIdx.x;
    const int pg = tid >> 3, cg = tid & 7;
    const int pr = pg >> 1, pc = (pg & 1) * 8;
    const int b = blockIdx.z >> 2;
    const int g = blockIdx.z & 3;
    const int co_base = g * 64;
    const int x0 = blockIdx.x * 16, y0 = blockIdx.y * 16;

    const uint32_t sA0 = (uint32_t)__cvta_generic_to_shared(sA);
    const uint32_t sB0 = (uint32_t)__cvta_generic_to_shared(sB);

    u64 acc2[8][4];
    #pragma unroll
    for (int m = 0; m < 8; m++)
        #pragma unroll
        for (int jp = 0; jp < 4; jp++) acc2[m][jp] = 0ULL;

    auto load_stage = [&](int st, int cb8) {
        const uint32_t sa = sA0 + st * (CONV_SA_STAGE*4);
        for (int e = tid; e < 8*18*18; e += 256) {
            int ci = e / 324; int rem = e - ci*324;
            int yy = rem / 18; int xx = rem - yy*18;
            int gy = y0 + yy - 1, gx = x0 + xx - 1;
            bool ok = (gy >= 0 && gy < 128 && gx >= 0 && gx < 128);
            int cy = gy < 0 ? 0 : (gy > 127 ? 127 : gy);
            int cx = gx < 0 ? 0 : (gx > 127 ? 127 : gx);
            cp_async4z(sa + e*4, &f[((b*256 + cb8*8 + ci)*128 + cy)*128 + cx], ok);
        }
        const float* ws = &d_wt[((g*32 + cb8)*72)*64];
        const uint32_t sb = sB0 + st * (CONV_SB_STAGE*4);
        for (int e = tid*4; e < 72*64; e += 1024)
            cp_async16(sb + e*4, ws + e);
    };

    load_stage(0, 0);
    CP_COMMIT();

    for (int cb8 = 0; cb8 < 32; cb8++) {
        const int cur = cb8 & 1;
        if (cb8 + 1 < 32) {
            load_stage(cur ^ 1, cb8 + 1);
            CP_COMMIT();
            CP_WAIT1();
        } else {
            CP_WAIT0();
        }
        __syncthreads();

        const float* sAc = sA + cur*CONV_SA_STAGE;
        const float* sBc = sB + cur*CONV_SB_STAGE;

        #pragma unroll
        for (int ci = 0; ci < 8; ci++) {
            #pragma unroll
            for (int ky = 0; ky < 3; ky++) {
                u64 aw[10];
                #pragma unroll
                for (int m = 0; m < 10; m++)
                    aw[m] = pack2(sAc[ci*324 + (pr + ky)*18 + pc + m]);
                #pragma unroll
                for (int kx = 0; kx < 3; kx++) {
                    const int kk = ci*9 + ky*3 + kx;
                    const ulonglong2 b01 = *(const ulonglong2*)&sBc[kk*64 + cg*8];
                    const ulonglong2 b23 = *(const ulonglong2*)&sBc[kk*64 + cg*8 + 4];
                    #pragma unroll
                    for (int m = 0; m < 8; m++) {
                        fma2(acc2[m][0], aw[kx + m], b01.x);
                        fma2(acc2[m][1], aw[kx + m], b01.y);
                        fma2(acc2[m][2], aw[kx + m], b23.x);
                        fma2(acc2[m][3], aw[kx + m], b23.y);
                    }
                }
            }
        }
        __syncthreads();
    }

    #pragma unroll
    for (int jp = 0; jp < 4; jp++) {
        const int co0 = co_base + cg*8 + jp*2;
        const float b0 = bias[co0], b1 = bias[co0 + 1];
        float v0[8], v1[8];
        #pragma unroll
        for (int m = 0; m < 8; m++) {
            float lo, hi;
            unpack2(acc2[m][jp], lo, hi);
            v0[m] = fmaxf(lo + b0, 0.f);
            v1[m] = fmaxf(hi + b1, 0.f);
        }
        float* p0 = &d_t[((b*256 + co0)*128 + (y0 + pr))*128 + (x0 + pc)];
        float* p1 = p0 + NPOS;
        *(float4*)p0       = make_float4(v0[0], v0[1], v0[2], v0[3]);
        *(float4*)(p0 + 4) = make_float4(v0[4], v0[5], v0[6], v0[7]);
        *(float4*)p1       = make_float4(v1[0], v1[1], v1[2], v1[3]);
        *(float4*)(p1 + 4) = make_float4(v1[4], v1[5], v1[6], v1[7]);
    }
}

// ---------------- selection helpers ----------------------------------------
__device__ __forceinline__ unsigned fkey(float s) {
    unsigned b = __float_as_uint(s);
    return (b & 0x80000000u) ? ~b : (b | 0x80000000u);  // monotone
}

// ---------------- K2: 1x1 heads, 15-out x 2-px, MLP-4 (R7, kept) ------------
// grid (32, 3, 4): x = px-block (512 px), y = out-group, z = img. 256 thr.
__global__ __launch_bounds__(256)
void k_heads(const float* __restrict__ cls_w, const float* __restrict__ cls_b,
             const float* __restrict__ bbox_w, const float* __restrict__ bbox_b)
{
    extern __shared__ __align__(16) u64 hsm[];
    u64* swd = hsm;                              // [256][16] duplicated weights
    float* sb = (float*)(hsm + 256*HOGP);        // [15] bias (+pad)
    unsigned* shist = (unsigned*)(sb + 16);      // [4096] (group 0 only)

    const int tid = threadIdx.x;
    const int g = blockIdx.y;
    const int b = blockIdx.z;

    for (int e = tid; e < 256*HOGP; e += 256) {
        int o = e & 15, c = e >> 4;
        float w = 0.f;
        if (o < HOG) {
            int ch = g*HOG + o;
            w = (ch < 9) ? cls_w[ch*256 + c] : bbox_w[(ch - 9)*256 + c];
        }
        swd[c*HOGP + o] = pack2(w);
    }
    if (tid < HOG) {
        int ch = g*HOG + tid;
        sb[tid] = (ch < 9) ? cls_b[ch] : bbox_b[ch - 9];
    }
    if (g == 0)
        for (int e = tid; e < BINS; e += 256) shist[e] = 0u;
    __syncthreads();

    const int px0 = blockIdx.x * 512 + tid * 2;

    u64 acc[HOG];
    #pragma unroll
    for (int o = 0; o < HOG; o++) acc[o] = 0ULL;

    const float* tbase = d_t + (size_t)b*CC*NPOS + px0;
    for (int c = 0; c < 256; c += 4) {
        u64 t[4];
        #pragma unroll
        for (int q = 0; q < 4; q++)
            t[q] = *(const u64*)(tbase + (size_t)(c + q)*NPOS);
        #pragma unroll
        for (int q = 0; q < 4; q++) {
            const u64* wr = &swd[(c + q)*HOGP];
            #pragma unroll
            for (int op = 0; op < 8; op++) {
                const ulonglong2 wv = *(const ulonglong2*)&wr[op*2];
                fma2(acc[op*2], t[q], wv.x);
                if (op*2 + 1 < HOG) fma2(acc[op*2 + 1], t[q], wv.y);
            }
        }
    }

    #pragma unroll
    for (int o = 0; o < HOG; o++) {
        const int ch = g*HOG + o;
        const float bv = sb[o];
        float v0, v1;
        unpack2(acc[o], v0, v1);
        if (ch < 9) {
            const float s0 = v0 + bv, s1 = v1 + bv;
            d_scores[(size_t)b*NANCH + (size_t)px0*9 + ch] = s0;
            d_scores[(size_t)b*NANCH + (size_t)(px0 + 1)*9 + ch] = s1;
            atomicAdd(&shist[fkey(s0) >> BIN_SHIFT], 1u);
            atomicAdd(&shist[fkey(s1) >> BIN_SHIFT], 1u);
        } else {
            const int dch = ch - 9;
            d_deltas[(size_t)b*NANCH*4 + (size_t)px0*36 + dch] = v0 + bv;
            d_deltas[(size_t)b*NANCH*4 + (size_t)(px0 + 1)*36 + dch] = v1 + bv;
        }
    }

    if (g == 0) {
        __syncthreads();
        for (int e = tid; e < BINS; e += 256)
            if (shist[e]) atomicAdd(&d_hist[b][e], shist[e]);
    }
}

__global__ void k_init() {
    int id = blockIdx.x * blockDim.x + threadIdx.x;
    if (id < BB*BINS) (&d_hist[0][0])[id] = 0u;
    if (id < BB) d_candcnt[id] = 0;
}

// suffix-sum over 4096 bins, pick highest bin with cum>=600
__global__ __launch_bounds__(1024) void k_thresh() {
    __shared__ unsigned suf[BINS + 1];
    const int tid = threadIdx.x;
    const int b = blockIdx.x;
    for (int e = tid; e < BINS; e += 1024) suf[e] = d_hist[b][e];
    if (tid == 0) suf[BINS] = 0u;
    __syncthreads();
    for (int off = 1; off < BINS; off <<= 1) {
        unsigned add[4];
        #pragma unroll
        for (int q = 0; q < 4; q++) {
            int i = tid + q*1024;
            add[q] = (i + off <= BINS) ? suf[i + off] : 0u;
        }
        __syncthreads();
        #pragma unroll
        for (int q = 0; q < 4; q++) suf[tid + q*1024] += add[q];
        __syncthreads();
    }
    #pragma unroll
    for (int q = 0; q < 4; q++) {
        int i = tid + q*1024;
        if (i < BINS && suf[i] >= PRE_K && suf[i+1] < PRE_K) d_thrbin[b] = i;
    }
}

__global__ void k_compact() {
    const int b = blockIdx.y;
    const int T = d_thrbin[b];
    const float* s = d_scores + (size_t)b*NANCH;
    for (unsigned i = blockIdx.x*blockDim.x + threadIdx.x; i < NANCH; i += gridDim.x*blockDim.x) {
        unsigned u = fkey(s[i]);
        if ((int)(u >> BIN_SHIFT) >= T) {
            int pos = atomicAdd(&d_candcnt[b], 1);
            if (pos < CAP)
                d_cand[b][pos] = ((unsigned long long)u << 32) | (unsigned)(~i);
        }
    }
}

__device__ __forceinline__ float read_dim(const void* p) {
    int i = *(const int*)p;
    float f = __int_as_float(i);
    return (i > 0 && i < (1 << 20)) ? (float)i : f;
}

// per-image: bitonic sort candidates desc by (score, then lower idx), decode top-600
__global__ __launch_bounds__(1024) void k_sortdecode(const void* ph, const void* pw) {
    __shared__ unsigned long long key[CAP];
    const int b = blockIdx.x;
    const int tid = threadIdx.x;
    int n = d_candcnt[b]; if (n > CAP) n = CAP;
    for (int e = tid; e < CAP; e += 1024) key[e] = (e < n) ? d_cand[b][e] : 0ULL;
    __syncthreads();

    for (int k = 2; k <= CAP; k <<= 1) {
        for (int j = k >> 1; j > 0; j >>= 1) {
            const int t = tid;
            const int i = ((t & ~(j - 1)) << 1) | (t & (j - 1));
            const int ixj = i | j;
            unsigned long long a = key[i], c = key[ixj];
            const bool up = ((i & k) == 0);
            if (up ? (a < c) : (a > c)) { key[i] = c; key[ixj] = a; }
            __syncthreads();
        }
    }

    if (tid < PRE_K) {
        const float img_h = read_dim(ph);
        const float img_w = read_dim(pw);
        const unsigned idx = ~(unsigned)(key[tid] & 0xFFFFFFFFULL);
        const int p = idx / 9, a = idx - 9*p;
        const float gx = (float)(p & 127) * 16.0f;
        const float gy = (float)(p >> 7) * 16.0f;
        const float hw = c_hw[a], hh = c_hh[a];
        const float x1 = gx - hw, y1 = gy - hh, x2 = gx + hw, y2 = gy + hh;
        const float w = x2 - x1, h = y2 - y1;
        const float cx = x1 + 0.5f*w, cy = y1 + 0.5f*h;
        const float4 dd = *(const float4*)&d_deltas[((size_t)b*NANCH + idx)*4];
        const float pcx = cx + dd.x * w;
        const float pcy = cy + dd.y * h;
        const float pw2 = w * expf(dd.z);
        const float ph2 = h * expf(dd.w);
        float4 o;
        o.x = fminf(fmaxf(pcx - 0.5f*pw2, 0.f), img_w);
        o.y = fminf(fmaxf(pcy - 0.5f*ph2, 0.f), img_h);
        o.z = fminf(fmaxf(pcx + 0.5f*pw2, 0.f), img_w);
        o.w = fminf(fmaxf(pcy + 0.5f*ph2, 0.f), img_h);
        *(float4*)&d_boxes[b][tid*4] = o;
    }
}

// 600x600 IoU suppression bitmask (j>i direction)
__global__ void k_mask() {
    const int id = blockIdx.x*blockDim.x + threadIdx.x;
    const int b = blockIdx.y;
    if (id >= PRE_K*NMS_WORDS) return;
    const int i = id / NMS_WORDS, wrd = id - i*NMS_WORDS;
    const float4 bi = *(const float4*)&d_boxes[b][i*4];
    const float areai = (bi.z - bi.x) * (bi.w - bi.y);
    unsigned m = 0u;
    const int j0 = wrd * 32;
    #pragma unroll 4
    for (int jj = 0; jj < 32; jj++) {
        const int j = j0 + jj;
        if (j > i && j < PRE_K) {
            const float4 bj = *(const float4*)&d_boxes[b][j*4];
            const float areaj = (bj.z - bj.x) * (bj.w - bj.y);
            const float xx1 = fmaxf(bi.x, bj.x), yy1 = fmaxf(bi.y, bj.y);
            const float xx2 = fminf(bi.z, bj.z), yy2 = fminf(bi.w, bj.w);
            const float inter = fmaxf(xx2 - xx1, 0.f) * fmaxf(yy2 - yy1, 0.f);
            const float iou = inter / (areai + areaj - inter);
            if (iou > 0.7f) m |= (1u << jj);
        }
    }
    d_mask[b][id] = m;
}

// serial suppression pass (single warp) + emit first 100 kept boxes
__global__ __launch_bounds__(128) void k_nms_out(float* __restrict__ out) {
    __shared__ unsigned smask[PRE_K*NMS_WORDS];
    __shared__ unsigned skeep[NMS_WORDS];
    __shared__ int s_sel[POST_K];
    __shared__ int s_cnt;
    const int b = blockIdx.x;
    const int tid = threadIdx.x;
    for (int e = tid; e < PRE_K*NMS_WORDS; e += 128) smask[e] = d_mask[b][e];
    __syncthreads();

    if (tid < 32) {
        unsigned rm = 0u;
        for (int i = 0; i < PRE_K; i++) {
            const unsigned wb = __shfl_sync(0xFFFFFFFFu, rm, i >> 5);
            if (!((wb >> (i & 31)) & 1u)) {
                if (tid < NMS_WORDS) rm |= smask[i*NMS_WORDS + tid];
            }
        }
        if (tid < NMS_WORDS) skeep[tid] = rm;
    }
    __syncthreads();
    if (tid == 0) {
        int cnt = 0;
        for (int j = 0; j < PRE_K && cnt < POST_K; j++)
            if (!((skeep[j >> 5] >> (j & 31)) & 1u)) s_sel[cnt++] = j;
        s_cnt = cnt;
    }
    __syncthreads();
    const int cnt = s_cnt;
    for (int k = tid; k < POST_K; k += 128) {
        float4 v = make_float4(0.f, 0.f, 0.f, 0.f);
        if (k < cnt) v = *(const float4*)&d_boxes[b][s_sel[k]*4];
        *(float4*)&out[(b*POST_K + k)*4] = v;
    }
}

// ---------------- launch ----------------------------------------------------
extern "C" void kernel_launch(void* const* d_in, const int* in_sizes, int n_in,
                              void* d_out, int out_size)
{
    const float* feats  = (const float*)d_in[0];
    const float* conv_w = (const float*)d_in[1];
    const float* conv_b = (const float*)d_in[2];
    const float* cls_w  = (const float*)d_in[3];
    const float* cls_b  = (const float*)d_in[4];
    const float* bbox_w = (const float*)d_in[5];
    const float* bbox_b = (const float*)d_in[6];
    const void*  ih     = d_in[7];
    const void*  iw     = d_in[8];

    cudaFuncSetAttribute(k_conv3, cudaFuncAttributeMaxDynamicSharedMemorySize,
                         CONV_SMEM_BYTES);
    cudaFuncSetAttribute(k_heads, cudaFuncAttributeMaxDynamicSharedMemorySize,
                         HEADS_SMEM_BYTES);

    k_init<<<64, 256>>>();
    k_wt<<<576, 1024>>>(conv_w);
    k_conv3<<<dim3(8, 8, 16), 256, CONV_SMEM_BYTES>>>(feats, conv_b);
    k_heads<<<dim3(32, 3, 4), 256, HEADS_SMEM_BYTES>>>(cls_w, cls_b, bbox_w, bbox_b);
    k_thresh<<<4, 1024>>>();
    k_compact<<<dim3(64, 4), 256>>>();
    k_sortdecode<<<4, 1024>>>(ih, iw);
    k_mask<<<dim3((PRE_K*NMS_WORDS + 255)/256, 4), 256>>>();
    k_nms_out<<<4, 128>>>((float*)d_out);
}